// round 7
// baseline (speedup 1.0000x reference)
#include <cuda_runtime.h>

// 2D single-level DWT (L=2, Haar): pure 2x2 stencil per output group.
// Input : x[b][r][c], b<64, r,c<512 (f32). Output: quadrants [[ll,hl],[lh,hh]].
//
// Model: kernel sits at the B300 LTS throughput cap (~6300 B/cyc) for its
// compulsory 128 MB of L2 traffic. R7 probes whether steady-state DRAM
// traffic adds on top: hybrid L2 residency targets ~120 MB resident
// (64 MB output via default stores + 56 MB input via default loads),
// streaming only the last 8 input images (__ldcs).
// Body = proven R1 mapping: 2x float4 loads, 4x float2 stores per thread.

#define RESIDENT_IMAGES 56  // images [0,56) default loads; [56,64) streamed

__global__ void __launch_bounds__(256) dwt_haar_kernel(
    const float* __restrict__ x,
    const float* __restrict__ lpf,
    const float* __restrict__ hpf,
    float* __restrict__ out)
{
    // t in [0,128): width-pair index, n in [0,256): subband row, b: batch
    const int gid = blockIdx.x * blockDim.x + threadIdx.x;
    const int t = gid & 127;
    const int n = (gid >> 7) & 255;
    const int b = gid >> 15;

    const long long img = (long long)b * (512 * 512);
    const float* p0 = x + img + (long long)(2 * n) * 512 + 4 * t;

    float4 r0, r1;
    if (b < RESIDENT_IMAGES) {
        r0 = *reinterpret_cast<const float4*>(p0);
        r1 = *reinterpret_cast<const float4*>(p0 + 512);
    } else {
        r0 = __ldcs(reinterpret_cast<const float4*>(p0));
        r1 = __ldcs(reinterpret_cast<const float4*>(p0 + 512));
    }

    const float lo0 = __ldg(&lpf[0]);
    const float lo1 = __ldg(&lpf[1]);
    const float hi0 = __ldg(&hpf[0]);
    const float hi1 = __ldg(&hpf[1]);

    float2 ll, lh, hl, hh;
    {
        float at = lo0 * r0.x + lo1 * r0.y, ab = lo0 * r1.x + lo1 * r1.y;
        float dt = hi0 * r0.x + hi1 * r0.y, db = hi0 * r1.x + hi1 * r1.y;
        ll.x = lo0 * at + lo1 * ab;  lh.x = hi0 * at + hi1 * ab;
        hl.x = lo0 * dt + lo1 * db;  hh.x = hi0 * dt + hi1 * db;
    }
    {
        float at = lo0 * r0.z + lo1 * r0.w, ab = lo0 * r1.z + lo1 * r1.w;
        float dt = hi0 * r0.z + hi1 * r0.w, db = hi0 * r1.z + hi1 * r1.w;
        ll.y = lo0 * at + lo1 * ab;  lh.y = hi0 * at + hi1 * ab;
        hl.y = lo0 * dt + lo1 * db;  hh.y = hi0 * dt + hi1 * db;
    }

    const int m = 2 * t;
    float* o_ll = out + img + (long long)n * 512 + m;
    float* o_lh = out + img + (long long)(n + 256) * 512 + m;

    // Default stores: output stays L2-resident, rewritten in place per replay.
    *reinterpret_cast<float2*>(o_ll)       = ll;
    *reinterpret_cast<float2*>(o_ll + 256) = hl;
    *reinterpret_cast<float2*>(o_lh)       = lh;
    *reinterpret_cast<float2*>(o_lh + 256) = hh;
}

extern "C" void kernel_launch(void* const* d_in, const int* in_sizes, int n_in,
                              void* d_out, int out_size)
{
    const float* x   = (const float*)d_in[0];
    const float* lpf = (const float*)d_in[1];
    const float* hpf = (const float*)d_in[2];
    float* out = (float*)d_out;

    const int total = 64 * 256 * 128;  // 2,097,152 threads
    dwt_haar_kernel<<<total / 256, 256>>>(x, lpf, hpf, out);
}